// round 15
// baseline (speedup 1.0000x reference)
#include <cuda_runtime.h>
#include <cuda_fp16.h>
#include <cstdint>

#define BATCH 2
#define SLEN  2048
#define DMODEL 1024
#define NHEAD 16
#define HDIM  64
#define NEG_BIG (-3.402823466e38f)
#define NEG_BM (-60000.0f)             // fits fp16; exp2(-60000 - m) == 0
#define LOG2E  1.4426950408889634f
#define LN_EPS 1e-6f
#define AP 72   // smem row pitch in halfs (144B: 16B-aligned, 4-bank rotate per row)

// Scratch (device globals: allocation-free, graph-capture safe)
__device__ __half g_q16[(size_t)BATCH * NHEAD * SLEN * HDIM];   // [B][H][S][HD]
__device__ __half g_k16[(size_t)BATCH * NHEAD * SLEN * HDIM];   // [B][H][S][HD]
__device__ __half g_v16[(size_t)BATCH * NHEAD * HDIM * SLEN];   // [B][H][HD][S] (transposed)
__device__ __half g_x16[(size_t)BATCH * SLEN * DMODEL];         // [B*S][D]
__device__ __half g_a16[(size_t)BATCH * SLEN * DMODEL];         // inputs_q as half
__device__ __half g_wqT[(size_t)DMODEL * DMODEL];               // W^T [n][k] half
__device__ __half g_wkT[(size_t)DMODEL * DMODEL];
__device__ __half g_wvT[(size_t)DMODEL * DMODEL];
__device__ __half g_woT[(size_t)DMODEL * DMODEL];
__device__ __half g_bm[(size_t)BATCH * SLEN * SLEN];            // (bias*log2e | -60000), fp16
__device__ int    g_mask_int32;

// ---------------------------------------------------------------------------
__device__ __forceinline__ void mma_f16(float4& c,
    unsigned a0, unsigned a1, unsigned a2, unsigned a3,
    unsigned b0, unsigned b1)
{
    asm volatile(
        "mma.sync.aligned.m16n8k16.row.col.f32.f16.f16.f32 "
        "{%0,%1,%2,%3}, {%4,%5,%6,%7}, {%8,%9}, {%0,%1,%2,%3};"
        : "+f"(c.x), "+f"(c.y), "+f"(c.z), "+f"(c.w)
        : "r"(a0), "r"(a1), "r"(a2), "r"(a3), "r"(b0), "r"(b1));
}
__device__ __forceinline__ void ldsm4(unsigned& r0, unsigned& r1, unsigned& r2, unsigned& r3,
                                      const __half* p)
{
    unsigned a = (unsigned)__cvta_generic_to_shared(p);
    asm volatile("ldmatrix.sync.aligned.m8n8.x4.shared.b16 {%0,%1,%2,%3}, [%4];"
                 : "=r"(r0), "=r"(r1), "=r"(r2), "=r"(r3) : "r"(a));
}
__device__ __forceinline__ void cp16(void* s, const void* g) {
    unsigned sa = (unsigned)__cvta_generic_to_shared(s);
    asm volatile("cp.async.ca.shared.global [%0], [%1], 16;" :: "r"(sa), "l"(g));
}
#define CP_COMMIT() asm volatile("cp.async.commit_group;")
#define CP_WAIT0()  asm volatile("cp.async.wait_group 0;")

__device__ __forceinline__ unsigned packh2(float a, float b) {
    __half2 h = __floats2half2_rn(a, b);
    return *reinterpret_cast<unsigned*>(&h);
}
__device__ __forceinline__ float2 unpackh2(unsigned u) {
    __half2 h = *reinterpret_cast<__half2*>(&u);
    return __half22float2(h);
}
__device__ __forceinline__ float ex2(float x) {
    float r;
    asm("ex2.approx.f32 %0, %1;" : "=f"(r) : "f"(x));
    return r;
}

// ---------------------------------------------------------------------------
__global__ void detect_mask_kernel(const unsigned char* __restrict__ m)
{
    int tid = threadIdx.x;
    unsigned int acc = 0;
    for (int i = tid; i < 4096; i += 32)
        if ((i & 3) != 0) acc |= m[i];
#pragma unroll
    for (int o = 16; o; o >>= 1) acc |= __shfl_xor_sync(0xffffffffu, acc, o);
    if (tid == 0) g_mask_int32 = (acc == 0) ? 1 : 0;
}

// store bias*log2e (or -60000 where masked) as fp16 — scores live in log2 domain
__global__ __launch_bounds__(256) void prep_bm_kernel(
    const float* __restrict__ bias, const unsigned char* __restrict__ mask)
{
    size_t i = ((size_t)blockIdx.x * blockDim.x + threadIdx.x) * 4;
    const size_t N = (size_t)BATCH * SLEN * SLEN;
    if (i >= N) return;
    float4 bv = *(const float4*)&bias[i];
    int mx, my, mz, mw;
    if (g_mask_int32) {
        int4 m = *(const int4*)((const int*)mask + i);
        mx = m.x; my = m.y; mz = m.z; mw = m.w;
    } else {
        uchar4 m = *(const uchar4*)(mask + i);
        mx = m.x; my = m.y; mz = m.z; mw = m.w;
    }
    uint2 o;
    o.x = packh2(mx ? bv.x * LOG2E : NEG_BM, my ? bv.y * LOG2E : NEG_BM);
    o.y = packh2(mz ? bv.z * LOG2E : NEG_BM, mw ? bv.w * LOG2E : NEG_BM);
    *reinterpret_cast<uint2*>(&g_bm[i]) = o;
}

// fp32 -> fp16 convert, 8 elements/thread
__global__ __launch_bounds__(256) void conv_half_kernel(
    const float4* __restrict__ src, __half* __restrict__ dst, int n8)
{
    int i = blockIdx.x * blockDim.x + threadIdx.x;
    if (i >= n8) return;
    float4 v0 = src[i * 2], v1 = src[i * 2 + 1];
    uint4 u;
    u.x = packh2(v0.x, v0.y); u.y = packh2(v0.z, v0.w);
    u.z = packh2(v1.x, v1.y); u.w = packh2(v1.z, v1.w);
    *reinterpret_cast<uint4*>(&dst[(size_t)i * 8]) = u;
}

// vectorized transpose+convert: WT[n][k] = half(W[k][n]).
// tile 64k x 32n, 256 threads: float4 gmem loads, uint4 fp16 stores.
__global__ __launch_bounds__(256) void wtrans_kernel(
    const float* __restrict__ Wq, const float* __restrict__ Wk,
    const float* __restrict__ Wv, const float* __restrict__ Wo,
    __half* __restrict__ Tq, __half* __restrict__ Tk,
    __half* __restrict__ Tv, __half* __restrict__ To)
{
    const float* W; __half* WT;
    switch (blockIdx.z) {
        case 0:  W = Wq; WT = Tq; break;
        case 1:  W = Wk; WT = Tk; break;
        case 2:  W = Wv; WT = Tv; break;
        default: W = Wo; WT = To; break;
    }
    __shared__ float t[64][33];
    const int n0 = blockIdx.x * 32, k0 = blockIdx.y * 64;
    const int tid = threadIdx.x;
#pragma unroll
    for (int it = 0; it < 2; it++) {
        int f = tid + it * 256;
        int kr = f >> 3, c4 = (f & 7) * 4;
        float4 v = *(const float4*)&W[(size_t)(k0 + kr) * DMODEL + n0 + c4];
        t[kr][c4] = v.x; t[kr][c4+1] = v.y; t[kr][c4+2] = v.z; t[kr][c4+3] = v.w;
    }
    __syncthreads();
    int n = tid >> 3, kc = (tid & 7) * 8;
    uint4 u;
    u.x = packh2(t[kc+0][n], t[kc+1][n]);
    u.y = packh2(t[kc+2][n], t[kc+3][n]);
    u.z = packh2(t[kc+4][n], t[kc+5][n]);
    u.w = packh2(t[kc+6][n], t[kc+7][n]);
    *(uint4*)&WT[(size_t)(n0 + n) * DMODEL + k0 + kc] = u;
}

// ---------------------------------------------------------------------------
// fp16 GEMM: 128x128 block, 8 warps (4x2) of 32x64, k-step 64, 2-stage
// cp.async, ONE sync per k-tile, ldmatrix fragment loads.
// MODE 0: QKV (grid.x=32; z=0: LN+0.125*log2e; z=1: LN; z=2: V^T). half out.
// MODE 1: out-proj quarter-chunk (grid.x=8): m-tile = (bx&3)+mbase+((bx>>2)<<4).
// ---------------------------------------------------------------------------
template<int MODE>
__global__ __launch_bounds__(256) void gemm_f16(
    const float* __restrict__ bq, const float* __restrict__ bk, const float* __restrict__ bv,
    const float* __restrict__ qs, const float* __restrict__ ksc,
    float* __restrict__ Cout, const float* __restrict__ bo, int mbase)
{
    extern __shared__ __half smh[];
    __half (*Ah)[128][AP] = (__half(*)[128][AP])smh;                 // 2 stages
    __half (*Bh)[128][AP] = (__half(*)[128][AP])(smh + 2 * 128 * AP);

    const __half* A; const __half* W; const float* bias;
    __half* C16 = nullptr; const float* sc = nullptr; float extra = 1.0f;
    int z = 0;
    if (MODE == 0) {
        z = blockIdx.z;
        A = g_a16;
        if (z == 0)      { W = g_wqT; bias = bq; C16 = g_q16; sc = qs;  extra = 0.125f * LOG2E; }
        else if (z == 1) { W = g_wkT; bias = bk; C16 = g_k16; sc = ksc; }
        else             { W = g_wvT; bias = bv; C16 = g_v16; }
    } else {
        A = g_x16; W = g_woT; bias = bo;
    }

    const int tid  = threadIdx.x;
    const int warp = tid >> 5, lane = tid & 31;
    const int grp  = lane >> 2, t4 = lane & 3;
    const int wm   = warp >> 1, wn = warp & 1;
    int bm;
    if (MODE == 0) bm = blockIdx.x * 128;
    else           bm = ((blockIdx.x & 3) + mbase + ((blockIdx.x >> 2) << 4)) * 128;
    const int bn   = blockIdx.y * 128;
    const int lrow = lane & 15, lcol = (lane >> 4) * 8;

    float4 acc[2][8];
#pragma unroll
    for (int mt = 0; mt < 2; mt++)
#pragma unroll
        for (int nt = 0; nt < 8; nt++) acc[mt][nt] = make_float4(0.f, 0.f, 0.f, 0.f);

    // prologue: k-tile 0 -> stage 0
#pragma unroll
    for (int it = 0; it < 4; it++) {
        int f = tid + it * 256;
        int r = f >> 3, c = (f & 7) * 8;
        cp16(&Ah[0][r][c], &A[(size_t)(bm + r) * DMODEL + c]);
        cp16(&Bh[0][r][c], &W[(size_t)(bn + r) * DMODEL + c]);
    }
    CP_COMMIT();

    const int T = DMODEL / 64;     // 16
    for (int s = 0; s < T; s++) {
        CP_WAIT0();
        __syncthreads();
        if (s + 1 < T) {
            int k0n = (s + 1) * 64, stn = (s + 1) & 1;
#pragma unroll
            for (int it = 0; it < 4; it++) {
                int f = tid + it * 256;
                int r = f >> 3, c = (f & 7) * 8;
                cp16(&Ah[stn][r][c], &A[(size_t)(bm + r) * DMODEL + k0n + c]);
                cp16(&Bh[stn][r][c], &W[(size_t)(bn + r) * DMODEL + k0n + c]);
            }
            CP_COMMIT();
        }

        const int st = s & 1;
        const __half* aptr = &Ah[st][wm * 32 + lrow][lcol];
        const __half* bptr = &Bh[st][wn * 64 + lrow][lcol];
#pragma unroll
        for (int kk = 0; kk < 4; kk++) {
            const int k16 = kk * 16;
            unsigned a[2][4];
#pragma unroll
            for (int mt = 0; mt < 2; mt++)
                ldsm4(a[mt][0], a[mt][1], a[mt][2], a[mt][3],
                      aptr + mt * 16 * AP + k16);
            unsigned bf[8][2];
#pragma unroll
            for (int p = 0; p < 4; p++)
                ldsm4(bf[2*p][0], bf[2*p+1][0], bf[2*p][1], bf[2*p+1][1],
                      bptr + p * 16 * AP + k16);
#pragma unroll
            for (int mt = 0; mt < 2; mt++)
#pragma unroll
                for (int nt = 0; nt < 8; nt++)
                    mma_f16(acc[mt][nt], a[mt][0], a[mt][1], a[mt][2], a[mt][3],
                            bf[nt][0], bf[nt][1]);
        }
    }

    // ---- epilogue: bias ----
    float bvx[8], bvy[8];
#pragma unroll
    for (int nt = 0; nt < 8; nt++) {
        int n = bn + wn * 64 + nt * 8 + 2 * t4;
        bvx[nt] = bias[n]; bvy[nt] = bias[n + 1];
    }
#pragma unroll
    for (int mt = 0; mt < 2; mt++)
#pragma unroll
        for (int nt = 0; nt < 8; nt++) {
            acc[mt][nt].x += bvx[nt]; acc[mt][nt].y += bvy[nt];
            acc[mt][nt].z += bvx[nt]; acc[mt][nt].w += bvy[nt];
        }

    if (MODE == 0 && z < 2) {
        float scx[8], scy[8];
#pragma unroll
        for (int nt = 0; nt < 8; nt++) {
            int e = nt * 8 + 2 * t4;
            scx[nt] = sc[e]; scy[nt] = sc[e + 1];
        }
#pragma unroll
        for (int mt = 0; mt < 2; mt++) {
            float sum_lo = 0.f, sq_lo = 0.f, sum_hi = 0.f, sq_hi = 0.f;
#pragma unroll
            for (int nt = 0; nt < 8; nt++) {
                float x = acc[mt][nt].x, y = acc[mt][nt].y;
                float zc = acc[mt][nt].z, w = acc[mt][nt].w;
                sum_lo += x + y;  sq_lo += x * x + y * y;
                sum_hi += zc + w; sq_hi += zc * zc + w * w;
            }
#pragma unroll
            for (int o = 1; o <= 2; o <<= 1) {
                sum_lo += __shfl_xor_sync(0xffffffffu, sum_lo, o);
                sq_lo  += __shfl_xor_sync(0xffffffffu, sq_lo,  o);
                sum_hi += __shfl_xor_sync(0xffffffffu, sum_hi, o);
                sq_hi  += __shfl_xor_sync(0xffffffffu, sq_hi,  o);
            }
            float mean_lo = sum_lo * (1.f / 64.f);
            float mean_hi = sum_hi * (1.f / 64.f);
            float var_lo = sq_lo * (1.f / 64.f) - mean_lo * mean_lo;
            float var_hi = sq_hi * (1.f / 64.f) - mean_hi * mean_hi;
            float r_lo = rsqrtf(var_lo + LN_EPS) * extra;
            float r_hi = rsqrtf(var_hi + LN_EPS) * extra;
#pragma unroll
            for (int nt = 0; nt < 8; nt++) {
                acc[mt][nt].x = (acc[mt][nt].x - mean_lo) * r_lo * scx[nt];
                acc[mt][nt].y = (acc[mt][nt].y - mean_lo) * r_lo * scy[nt];
                acc[mt][nt].z = (acc[mt][nt].z - mean_hi) * r_hi * scx[nt];
                acc[mt][nt].w = (acc[mt][nt].w - mean_hi) * r_hi * scy[nt];
            }
        }
    }

#pragma unroll
    for (int mt = 0; mt < 2; mt++) {
#pragma unroll
        for (int nt = 0; nt < 8; nt++) {
            int m = bm + wm * 32 + mt * 16 + grp;
            int n = bn + wn * 64 + nt * 8 + 2 * t4;
            if (MODE == 1) {
                *(float2*)&Cout[(size_t)m * DMODEL + n] =
                    make_float2(acc[mt][nt].x, acc[mt][nt].y);
                *(float2*)&Cout[(size_t)(m + 8) * DMODEL + n] =
                    make_float2(acc[mt][nt].z, acc[mt][nt].w);
            } else {
                int bb = m >> 11, hh = n >> 6, e = n & (HDIM - 1);
                int s_lo = m & (SLEN - 1), s_hi = (m + 8) & (SLEN - 1);
                if (z < 2) {
                    size_t base = ((size_t)((bb * NHEAD + hh) * SLEN)) * HDIM;
                    *(unsigned*)&C16[base + (size_t)s_lo * HDIM + e] =
                        packh2(acc[mt][nt].x, acc[mt][nt].y);
                    *(unsigned*)&C16[base + (size_t)s_hi * HDIM + e] =
                        packh2(acc[mt][nt].z, acc[mt][nt].w);
                } else {
                    size_t base = ((size_t)((bb * NHEAD + hh) * HDIM)) * SLEN;
                    C16[base + (size_t)e * SLEN + s_lo]       = __float2half_rn(acc[mt][nt].x);
                    C16[base + (size_t)(e + 1) * SLEN + s_lo] = __float2half_rn(acc[mt][nt].y);
                    C16[base + (size_t)e * SLEN + s_hi]       = __float2half_rn(acc[mt][nt].z);
                    C16[base + (size_t)(e + 1) * SLEN + s_hi] = __float2half_rn(acc[mt][nt].w);
                }
            }
        }
    }
}

// ---------------------------------------------------------------------------
// fp16 flash attention (q-chunked). grid.x = 4 per chunk; q0 = (bx+qoff)*128.
// ---------------------------------------------------------------------------
__global__ __launch_bounds__(256) void attn_f16(int qoff)
{
    extern __shared__ __half smh[];
    __half (*Kh)[64][AP] = (__half(*)[64][AP])smh;                    // [2][kv][e]
    __half (*Vt)[64][AP] = (__half(*)[64][AP])(smh + 2 * 64 * AP);    // [2][e][kv]

    const int tid  = threadIdx.x;
    const int warp = tid >> 5, lane = tid & 31;
    const int grp  = lane >> 2, t4 = lane & 3;
    const int m0   = warp * 16;
    const int q0   = (blockIdx.x + qoff) * 128;
    const int h    = blockIdx.y, b = blockIdx.z;
    const int lrow = lane & 15, lcol = (lane >> 4) * 8;

    const __half* qh = g_q16 + ((size_t)(b * NHEAD + h)) * SLEN * HDIM;
    const __half* kh = g_k16 + ((size_t)(b * NHEAD + h)) * SLEN * HDIM;
    const __half* vt = g_v16 + ((size_t)(b * NHEAD + h)) * HDIM * SLEN;
    const __half* bmb = g_bm + (size_t)b * SLEN * SLEN;

#pragma unroll
    for (int it = 0; it < 4; it++) {
        int f = tid + it * 256;
        int r = f >> 3, c = (f & 7) * 8;
        cp16(smh + (size_t)r * AP + c, &qh[(size_t)(q0 + r) * HDIM + c]);
    }
    CP_COMMIT();
    CP_WAIT0();
    __syncthreads();

    unsigned qa[4][4];
    {
        const __half* qptr = smh + (size_t)(m0 + lrow) * AP + lcol;
#pragma unroll
        for (int kk = 0; kk < 4; kk++)
            ldsm4(qa[kk][0], qa[kk][1], qa[kk][2], qa[kk][3], qptr + kk * 16);
    }
    __syncthreads();

#pragma unroll
    for (int it = 0; it < 2; it++) {
        int f = tid + it * 256;
        int r = f >> 3, c = (f & 7) * 8;
        cp16(&Kh[0][r][c], &kh[(size_t)r * HDIM + c]);
        cp16(&Vt[0][r][c], &vt[(size_t)r * SLEN + c]);
    }
    CP_COMMIT();

    float4 X[8];
#pragma unroll
    for (int nt = 0; nt < 8; nt++) X[nt] = make_float4(0.f, 0.f, 0.f, 0.f);
    float m_lo = NEG_BIG, m_hi = NEG_BIG, l_lo = 0.f, l_hi = 0.f;

    const __half* bm_lo_base = &bmb[(size_t)(q0 + m0 + grp) * SLEN];
    const __half* bm_hi_base = bm_lo_base + (size_t)8 * SLEN;

    const int T = SLEN / 64;       // 32
    for (int s = 0; s < T; s++) {
        CP_WAIT0();
        __syncthreads();
        if (s + 1 < T) {
            int k0n = (s + 1) * 64, stn = (s + 1) & 1;
#pragma unroll
            for (int it = 0; it < 2; it++) {
                int f = tid + it * 256;
                int r = f >> 3, c = (f & 7) * 8;
                cp16(&Kh[stn][r][c], &kh[(size_t)(k0n + r) * HDIM + c]);
                cp16(&Vt[stn][r][c], &vt[(size_t)r * SLEN + k0n + c]);
            }
            CP_COMMIT();
        }

        const int st = s & 1;
        const int k0 = s * 64;
        const __half* kptr = &Kh[st][lrow][lcol];
        const __half* vptr = &Vt[st][lrow][lcol];

        unsigned pbl[8], pbh[8];
#pragma unroll
        for (int nt = 0; nt < 8; nt++) {
            pbl[nt] = *(const unsigned*)&bm_lo_base[k0 + nt * 8 + 2 * t4];
            pbh[nt] = *(const unsigned*)&bm_hi_base[k0 + nt * 8 + 2 * t4];
        }

        float4 sv[8];
#pragma unroll
        for (int nt = 0; nt < 8; nt++) sv[nt] = make_float4(0.f, 0.f, 0.f, 0.f);
#pragma unroll
        for (int kk = 0; kk < 4; kk++) {
            const int k16 = kk * 16;
            unsigned kf[8][2];
#pragma unroll
            for (int p = 0; p < 4; p++)
                ldsm4(kf[2*p][0], kf[2*p+1][0], kf[2*p][1], kf[2*p+1][1],
                      kptr + p * 16 * AP + k16);
#pragma unroll
            for (int nt = 0; nt < 8; nt++)
                mma_f16(sv[nt], qa[kk][0], qa[kk][1], qa[kk][2], qa[kk][3],
                        kf[nt][0], kf[nt][1]);
        }

        float mx_lo = NEG_BIG, mx_hi = NEG_BIG;
#pragma unroll
        for (int nt = 0; nt < 8; nt++) {
            float2 blo = unpackh2(pbl[nt]);
            float2 bhi = unpackh2(pbh[nt]);
            sv[nt].x += blo.x; sv[nt].y += blo.y;
            sv[nt].z += bhi.x; sv[nt].w += bhi.y;
            mx_lo = fmaxf(mx_lo, fmaxf(sv[nt].x, sv[nt].y));
            mx_hi = fmaxf(mx_hi, fmaxf(sv[nt].z, sv[nt].w));
        }
        mx_lo = fmaxf(mx_lo, __shfl_xor_sync(0xffffffffu, mx_lo, 1));
        mx_lo = fmaxf(mx_lo, __shfl_xor_sync(0xffffffffu, mx_lo, 2));
        mx_hi = fmaxf(mx_hi, __shfl_xor_sync(0xffffffffu, mx_hi, 1));
        mx_hi = fmaxf(mx_hi, __shfl_xor_sync(0xffffffffu, mx_hi, 2));

        float mn_lo = fmaxf(m_lo, mx_lo), mn_hi = fmaxf(m_hi, mx_hi);
        float cor_lo = ex2(m_lo - mn_lo), cor_hi = ex2(m_hi - mn_hi);
        m_lo = mn_lo; m_hi = mn_hi;

        float rs_lo = 0.f, rs_hi = 0.f;
#pragma unroll
        for (int nt = 0; nt < 8; nt++) {
            sv[nt].x = ex2(sv[nt].x - mn_lo);
            sv[nt].y = ex2(sv[nt].y - mn_lo);
            sv[nt].z = ex2(sv[nt].z - mn_hi);
            sv[nt].w = ex2(sv[nt].w - mn_hi);
            rs_lo += sv[nt].x + sv[nt].y;
            rs_hi += sv[nt].z + sv[nt].w;
        }
        l_lo = l_lo * cor_lo + rs_lo;
        l_hi = l_hi * cor_hi + rs_hi;
#pragma unroll
        for (int nt = 0; nt < 8; nt++) {
            X[nt].x *= cor_lo; X[nt].y *= cor_lo;
            X[nt].z *= cor_hi; X[nt].w *= cor_hi;
        }

#pragma unroll
        for (int kk = 0; kk < 4; kk++) {
            const int k16 = kk * 16;
            unsigned pa0 = packh2(sv[2*kk].x,     sv[2*kk].y);
            unsigned pa1 = packh2(sv[2*kk].z,     sv[2*kk].w);
            unsigned pa2 = packh2(sv[2*kk + 1].x, sv[2*kk + 1].y);
            unsigned pa3 = packh2(sv[2*kk + 1].z, sv[2*kk + 1].w);
            unsigned vf[8][2];
#pragma unroll
            for (int p = 0; p < 4; p++)
                ldsm4(vf[2*p][0], vf[2*p+1][0], vf[2*p][1], vf[2*p+1][1],
                      vptr + p * 16 * AP + k16);
#pragma unroll
            for (int nt = 0; nt < 8; nt++)
                mma_f16(X[nt], pa0, pa1, pa2, pa3, vf[nt][0], vf[nt][1]);
        }
    }

    l_lo += __shfl_xor_sync(0xffffffffu, l_lo, 1);
    l_lo += __shfl_xor_sync(0xffffffffu, l_lo, 2);
    l_hi += __shfl_xor_sync(0xffffffffu, l_hi, 1);
    l_hi += __shfl_xor_sync(0xffffffffu, l_hi, 2);
    float il_lo = 1.f / l_lo, il_hi = 1.f / l_hi;
    int r_lo = q0 + m0 + grp, r_hi = r_lo + 8;
#pragma unroll
    for (int nt = 0; nt < 8; nt++) {
        int col = h * HDIM + nt * 8 + 2 * t4;
        *(unsigned*)&g_x16[(size_t)(b * SLEN + r_lo) * DMODEL + col] =
            packh2(X[nt].x * il_lo, X[nt].y * il_lo);
        *(unsigned*)&g_x16[(size_t)(b * SLEN + r_hi) * DMODEL + col] =
            packh2(X[nt].z * il_hi, X[nt].w * il_hi);
    }
}

// ---------------------------------------------------------------------------
extern "C" void kernel_launch(void* const* d_in, const int* in_sizes, int n_in,
                              void* d_out, int out_size)
{
    const float*         inputs_q = (const float*)d_in[0];
    const float*         bias     = (const float*)d_in[1];
    const unsigned char* mask     = (const unsigned char*)d_in[2];
    const float*         wq       = (const float*)d_in[3];
    const float*         bq       = (const float*)d_in[4];
    const float*         wk       = (const float*)d_in[5];
    const float*         bk       = (const float*)d_in[6];
    const float*         wv       = (const float*)d_in[7];
    const float*         bv       = (const float*)d_in[8];
    const float*         q_scale  = (const float*)d_in[9];
    const float*         k_scale  = (const float*)d_in[10];
    const float*         wo       = (const float*)d_in[11];
    const float*         bo       = (const float*)d_in[12];
    float*               out      = (float*)d_out;

    const int GEMM_SMEM = 2 * 2 * 128 * AP * 2;            // 73728 B
    const int ATTN_SMEM = 4 * 64 * AP * 2;                 // 36864 B

    static bool init_done = false;
    static cudaStream_t s1, s2, s3;
    static cudaEvent_t evFork, evBM, evWT, evQKV, evDone;
    static __half *p_wqT, *p_wkT, *p_wvT, *p_woT, *p_a16;
    if (!init_done) {
        cudaFuncSetAttribute(gemm_f16<0>, cudaFuncAttributeMaxDynamicSharedMemorySize, GEMM_SMEM);
        cudaFuncSetAttribute(gemm_f16<1>, cudaFuncAttributeMaxDynamicSharedMemorySize, GEMM_SMEM);
        cudaFuncSetAttribute(attn_f16, cudaFuncAttributeMaxDynamicSharedMemorySize, ATTN_SMEM);
        cudaGetSymbolAddress((void**)&p_wqT, g_wqT);
        cudaGetSymbolAddress((void**)&p_wkT, g_wkT);
        cudaGetSymbolAddress((void**)&p_wvT, g_wvT);
        cudaGetSymbolAddress((void**)&p_woT, g_woT);
        cudaGetSymbolAddress((void**)&p_a16, g_a16);
        cudaStreamCreateWithFlags(&s1, cudaStreamNonBlocking);
        cudaStreamCreateWithFlags(&s2, cudaStreamNonBlocking);
        cudaStreamCreateWithFlags(&s3, cudaStreamNonBlocking);
        cudaEventCreateWithFlags(&evFork, cudaEventDisableTiming);
        cudaEventCreateWithFlags(&evBM,   cudaEventDisableTiming);
        cudaEventCreateWithFlags(&evWT,   cudaEventDisableTiming);
        cudaEventCreateWithFlags(&evQKV,  cudaEventDisableTiming);
        cudaEventCreateWithFlags(&evDone, cudaEventDisableTiming);
        init_done = true;
    }

    // fork point
    cudaEventRecord(evFork, 0);

    // s1: bias/mask chain (feeds attention only)
    cudaStreamWaitEvent(s1, evFork, 0);
    detect_mask_kernel<<<1, 32, 0, s1>>>(mask);
    {
        const size_t N = (size_t)BATCH * SLEN * SLEN;
        prep_bm_kernel<<<(int)((N / 4 + 255) / 256), 256, 0, s1>>>(bias, mask);
    }
    cudaEventRecord(evBM, s1);

    // s2: weight transposes (feed gemm0/gemm1)
    cudaStreamWaitEvent(s2, evFork, 0);
    wtrans_kernel<<<dim3(32, 16, 4), 256, 0, s2>>>(wq, wk, wv, wo,
                                                   p_wqT, p_wkT, p_wvT, p_woT);
    cudaEventRecord(evWT, s2);

    // main: input conversion (concurrent with wtrans) -> QKV gemm
    const int A8 = BATCH * SLEN * DMODEL / 8;
    conv_half_kernel<<<(A8 + 255) / 256, 256>>>((const float4*)inputs_q, p_a16, A8);
    cudaStreamWaitEvent(0, evWT, 0);
    gemm_f16<0><<<dim3(32, 8, 3), 256, GEMM_SMEM>>>(bq, bk, bv, q_scale, k_scale,
                                                    nullptr, nullptr, 0);
    cudaEventRecord(evQKV, 0);

    // 4 attn->O-proj chunks interleaved on two streams:
    // main: c=0, c=2 ; s3: c=1, c=3. Chunk c: q-tiles [4c, 4c+4), m-tiles {4c..}∪{16+4c..}.
    cudaStreamWaitEvent(0, evBM, 0);
    cudaStreamWaitEvent(s3, evQKV, 0);
    cudaStreamWaitEvent(s3, evBM, 0);

    attn_f16<<<dim3(4, NHEAD, BATCH), 256, ATTN_SMEM>>>(0);
    attn_f16<<<dim3(4, NHEAD, BATCH), 256, ATTN_SMEM, s3>>>(4);
    gemm_f16<1><<<dim3(8, 8), 256, GEMM_SMEM>>>(nullptr, nullptr, nullptr, nullptr, nullptr,
                                                out, bo, 0);
    gemm_f16<1><<<dim3(8, 8), 256, GEMM_SMEM, s3>>>(nullptr, nullptr, nullptr, nullptr, nullptr,
                                                    out, bo, 4);
    attn_f16<<<dim3(4, NHEAD, BATCH), 256, ATTN_SMEM>>>(8);
    attn_f16<<<dim3(4, NHEAD, BATCH), 256, ATTN_SMEM, s3>>>(12);
    gemm_f16<1><<<dim3(8, 8), 256, GEMM_SMEM>>>(nullptr, nullptr, nullptr, nullptr, nullptr,
                                                out, bo, 8);
    gemm_f16<1><<<dim3(8, 8), 256, GEMM_SMEM, s3>>>(nullptr, nullptr, nullptr, nullptr, nullptr,
                                                    out, bo, 12);
    cudaEventRecord(evDone, s3);

    // join chunk stream back into the main stream
    cudaStreamWaitEvent(0, evDone, 0);
}

// round 16
// speedup vs baseline: 1.0577x; 1.0577x over previous
#include <cuda_runtime.h>
#include <cuda_fp16.h>
#include <cstdint>

#define BATCH 2
#define SLEN  2048
#define DMODEL 1024
#define NHEAD 16
#define HDIM  64
#define NEG_BIG (-3.402823466e38f)
#define NEG_BM (-60000.0f)             // fits fp16; exp2(-60000 - m) == 0
#define LOG2E  1.4426950408889634f
#define LN_EPS 1e-6f
#define AP 72   // smem row pitch in halfs (144B: 16B-aligned, 4-bank rotate per row)

// Scratch (device globals: allocation-free, graph-capture safe)
__device__ __half g_q16[(size_t)BATCH * NHEAD * SLEN * HDIM];   // [B][H][S][HD]
__device__ __half g_k16[(size_t)BATCH * NHEAD * SLEN * HDIM];   // [B][H][S][HD]
__device__ __half g_v16[(size_t)BATCH * NHEAD * HDIM * SLEN];   // [B][H][HD][S] (transposed)
__device__ __half g_x16[(size_t)BATCH * SLEN * DMODEL];         // [B*S][D]
__device__ __half g_a16[(size_t)BATCH * SLEN * DMODEL];         // inputs_q as half
__device__ __half g_wqT[(size_t)DMODEL * DMODEL];               // W^T [n][k] half
__device__ __half g_wkT[(size_t)DMODEL * DMODEL];
__device__ __half g_wvT[(size_t)DMODEL * DMODEL];
__device__ __half g_woT[(size_t)DMODEL * DMODEL];
__device__ __half g_bm[(size_t)BATCH * SLEN * SLEN];            // (bias*log2e | -60000), fp16
__device__ int    g_mask_int32;

// ---------------------------------------------------------------------------
__device__ __forceinline__ void mma_f16(float4& c,
    unsigned a0, unsigned a1, unsigned a2, unsigned a3,
    unsigned b0, unsigned b1)
{
    asm volatile(
        "mma.sync.aligned.m16n8k16.row.col.f32.f16.f16.f32 "
        "{%0,%1,%2,%3}, {%4,%5,%6,%7}, {%8,%9}, {%0,%1,%2,%3};"
        : "+f"(c.x), "+f"(c.y), "+f"(c.z), "+f"(c.w)
        : "r"(a0), "r"(a1), "r"(a2), "r"(a3), "r"(b0), "r"(b1));
}
__device__ __forceinline__ void ldsm4(unsigned& r0, unsigned& r1, unsigned& r2, unsigned& r3,
                                      const __half* p)
{
    unsigned a = (unsigned)__cvta_generic_to_shared(p);
    asm volatile("ldmatrix.sync.aligned.m8n8.x4.shared.b16 {%0,%1,%2,%3}, [%4];"
                 : "=r"(r0), "=r"(r1), "=r"(r2), "=r"(r3) : "r"(a));
}
__device__ __forceinline__ void cp16(void* s, const void* g) {
    unsigned sa = (unsigned)__cvta_generic_to_shared(s);
    asm volatile("cp.async.ca.shared.global [%0], [%1], 16;" :: "r"(sa), "l"(g));
}
#define CP_COMMIT() asm volatile("cp.async.commit_group;")
#define CP_WAIT0()  asm volatile("cp.async.wait_group 0;")

__device__ __forceinline__ unsigned packh2(float a, float b) {
    __half2 h = __floats2half2_rn(a, b);
    return *reinterpret_cast<unsigned*>(&h);
}
__device__ __forceinline__ float2 unpackh2(unsigned u) {
    __half2 h = *reinterpret_cast<__half2*>(&u);
    return __half22float2(h);
}
__device__ __forceinline__ float ex2(float x) {
    float r;
    asm("ex2.approx.f32 %0, %1;" : "=f"(r) : "f"(x));
    return r;
}

// ---------------------------------------------------------------------------
__global__ void detect_mask_kernel(const unsigned char* __restrict__ m)
{
    int tid = threadIdx.x;
    unsigned int acc = 0;
    for (int i = tid; i < 4096; i += 32)
        if ((i & 3) != 0) acc |= m[i];
#pragma unroll
    for (int o = 16; o; o >>= 1) acc |= __shfl_xor_sync(0xffffffffu, acc, o);
    if (tid == 0) g_mask_int32 = (acc == 0) ? 1 : 0;
}

// store bias*log2e (or -60000 where masked) as fp16 — scores live in log2 domain
__global__ __launch_bounds__(256) void prep_bm_kernel(
    const float* __restrict__ bias, const unsigned char* __restrict__ mask)
{
    size_t i = ((size_t)blockIdx.x * blockDim.x + threadIdx.x) * 4;
    const size_t N = (size_t)BATCH * SLEN * SLEN;
    if (i >= N) return;
    float4 bv = *(const float4*)&bias[i];
    int mx, my, mz, mw;
    if (g_mask_int32) {
        int4 m = *(const int4*)((const int*)mask + i);
        mx = m.x; my = m.y; mz = m.z; mw = m.w;
    } else {
        uchar4 m = *(const uchar4*)(mask + i);
        mx = m.x; my = m.y; mz = m.z; mw = m.w;
    }
    uint2 o;
    o.x = packh2(mx ? bv.x * LOG2E : NEG_BM, my ? bv.y * LOG2E : NEG_BM);
    o.y = packh2(mz ? bv.z * LOG2E : NEG_BM, mw ? bv.w * LOG2E : NEG_BM);
    *reinterpret_cast<uint2*>(&g_bm[i]) = o;
}

// fp32 -> fp16 convert, 8 elements/thread
__global__ __launch_bounds__(256) void conv_half_kernel(
    const float4* __restrict__ src, __half* __restrict__ dst, int n8)
{
    int i = blockIdx.x * blockDim.x + threadIdx.x;
    if (i >= n8) return;
    float4 v0 = src[i * 2], v1 = src[i * 2 + 1];
    uint4 u;
    u.x = packh2(v0.x, v0.y); u.y = packh2(v0.z, v0.w);
    u.z = packh2(v1.x, v1.y); u.w = packh2(v1.z, v1.w);
    *reinterpret_cast<uint4*>(&dst[(size_t)i * 8]) = u;
}

// vectorized transpose+convert: WT[n][k] = half(W[k][n]).
// tile 64k x 32n, 256 threads: float4 gmem loads, uint4 fp16 stores.
__global__ __launch_bounds__(256) void wtrans_kernel(
    const float* __restrict__ Wq, const float* __restrict__ Wk,
    const float* __restrict__ Wv, const float* __restrict__ Wo,
    __half* __restrict__ Tq, __half* __restrict__ Tk,
    __half* __restrict__ Tv, __half* __restrict__ To)
{
    const float* W; __half* WT;
    switch (blockIdx.z) {
        case 0:  W = Wq; WT = Tq; break;
        case 1:  W = Wk; WT = Tk; break;
        case 2:  W = Wv; WT = Tv; break;
        default: W = Wo; WT = To; break;
    }
    __shared__ float t[64][33];
    const int n0 = blockIdx.x * 32, k0 = blockIdx.y * 64;
    const int tid = threadIdx.x;
#pragma unroll
    for (int it = 0; it < 2; it++) {
        int f = tid + it * 256;
        int kr = f >> 3, c4 = (f & 7) * 4;
        float4 v = *(const float4*)&W[(size_t)(k0 + kr) * DMODEL + n0 + c4];
        t[kr][c4] = v.x; t[kr][c4+1] = v.y; t[kr][c4+2] = v.z; t[kr][c4+3] = v.w;
    }
    __syncthreads();
    int n = tid >> 3, kc = (tid & 7) * 8;
    uint4 u;
    u.x = packh2(t[kc+0][n], t[kc+1][n]);
    u.y = packh2(t[kc+2][n], t[kc+3][n]);
    u.z = packh2(t[kc+4][n], t[kc+5][n]);
    u.w = packh2(t[kc+6][n], t[kc+7][n]);
    *(uint4*)&WT[(size_t)(n0 + n) * DMODEL + k0 + kc] = u;
}

// ---------------------------------------------------------------------------
// fp16 GEMM: 128x128 block, 8 warps (4x2) of 32x64, k-step 64, 2-stage
// cp.async, ONE sync per k-tile, ldmatrix fragment loads.
// MODE 0: QKV (grid.x=32; z=0: LN+0.125*log2e; z=1: LN; z=2: V^T). half out.
// MODE 1: out-proj chunk (grid.x=16): m-tile = (bx&7)+mbase+((bx>>3)<<4).
// ---------------------------------------------------------------------------
template<int MODE>
__global__ __launch_bounds__(256) void gemm_f16(
    const float* __restrict__ bq, const float* __restrict__ bk, const float* __restrict__ bv,
    const float* __restrict__ qs, const float* __restrict__ ksc,
    float* __restrict__ Cout, const float* __restrict__ bo, int mbase)
{
    extern __shared__ __half smh[];
    __half (*Ah)[128][AP] = (__half(*)[128][AP])smh;                 // 2 stages
    __half (*Bh)[128][AP] = (__half(*)[128][AP])(smh + 2 * 128 * AP);

    const __half* A; const __half* W; const float* bias;
    __half* C16 = nullptr; const float* sc = nullptr; float extra = 1.0f;
    int z = 0;
    if (MODE == 0) {
        z = blockIdx.z;
        A = g_a16;
        if (z == 0)      { W = g_wqT; bias = bq; C16 = g_q16; sc = qs;  extra = 0.125f * LOG2E; }
        else if (z == 1) { W = g_wkT; bias = bk; C16 = g_k16; sc = ksc; }
        else             { W = g_wvT; bias = bv; C16 = g_v16; }
    } else {
        A = g_x16; W = g_woT; bias = bo;
    }

    const int tid  = threadIdx.x;
    const int warp = tid >> 5, lane = tid & 31;
    const int grp  = lane >> 2, t4 = lane & 3;
    const int wm   = warp >> 1, wn = warp & 1;
    int bm;
    if (MODE == 0) bm = blockIdx.x * 128;
    else           bm = ((blockIdx.x & 7) + mbase + ((blockIdx.x >> 3) << 4)) * 128;
    const int bn   = blockIdx.y * 128;
    const int lrow = lane & 15, lcol = (lane >> 4) * 8;

    float4 acc[2][8];
#pragma unroll
    for (int mt = 0; mt < 2; mt++)
#pragma unroll
        for (int nt = 0; nt < 8; nt++) acc[mt][nt] = make_float4(0.f, 0.f, 0.f, 0.f);

    // prologue: k-tile 0 -> stage 0
#pragma unroll
    for (int it = 0; it < 4; it++) {
        int f = tid + it * 256;
        int r = f >> 3, c = (f & 7) * 8;
        cp16(&Ah[0][r][c], &A[(size_t)(bm + r) * DMODEL + c]);
        cp16(&Bh[0][r][c], &W[(size_t)(bn + r) * DMODEL + c]);
    }
    CP_COMMIT();

    const int T = DMODEL / 64;     // 16
    for (int s = 0; s < T; s++) {
        CP_WAIT0();
        __syncthreads();
        if (s + 1 < T) {
            int k0n = (s + 1) * 64, stn = (s + 1) & 1;
#pragma unroll
            for (int it = 0; it < 4; it++) {
                int f = tid + it * 256;
                int r = f >> 3, c = (f & 7) * 8;
                cp16(&Ah[stn][r][c], &A[(size_t)(bm + r) * DMODEL + k0n + c]);
                cp16(&Bh[stn][r][c], &W[(size_t)(bn + r) * DMODEL + k0n + c]);
            }
            CP_COMMIT();
        }

        const int st = s & 1;
        const __half* aptr = &Ah[st][wm * 32 + lrow][lcol];
        const __half* bptr = &Bh[st][wn * 64 + lrow][lcol];
#pragma unroll
        for (int kk = 0; kk < 4; kk++) {
            const int k16 = kk * 16;
            unsigned a[2][4];
#pragma unroll
            for (int mt = 0; mt < 2; mt++)
                ldsm4(a[mt][0], a[mt][1], a[mt][2], a[mt][3],
                      aptr + mt * 16 * AP + k16);
            unsigned bf[8][2];
#pragma unroll
            for (int p = 0; p < 4; p++)
                ldsm4(bf[2*p][0], bf[2*p+1][0], bf[2*p][1], bf[2*p+1][1],
                      bptr + p * 16 * AP + k16);
#pragma unroll
            for (int mt = 0; mt < 2; mt++)
#pragma unroll
                for (int nt = 0; nt < 8; nt++)
                    mma_f16(acc[mt][nt], a[mt][0], a[mt][1], a[mt][2], a[mt][3],
                            bf[nt][0], bf[nt][1]);
        }
    }

    // ---- epilogue: bias ----
    float bvx[8], bvy[8];
#pragma unroll
    for (int nt = 0; nt < 8; nt++) {
        int n = bn + wn * 64 + nt * 8 + 2 * t4;
        bvx[nt] = bias[n]; bvy[nt] = bias[n + 1];
    }
#pragma unroll
    for (int mt = 0; mt < 2; mt++)
#pragma unroll
        for (int nt = 0; nt < 8; nt++) {
            acc[mt][nt].x += bvx[nt]; acc[mt][nt].y += bvy[nt];
            acc[mt][nt].z += bvx[nt]; acc[mt][nt].w += bvy[nt];
        }

    if (MODE == 0 && z < 2) {
        float scx[8], scy[8];
#pragma unroll
        for (int nt = 0; nt < 8; nt++) {
            int e = nt * 8 + 2 * t4;
            scx[nt] = sc[e]; scy[nt] = sc[e + 1];
        }
#pragma unroll
        for (int mt = 0; mt < 2; mt++) {
            float sum_lo = 0.f, sq_lo = 0.f, sum_hi = 0.f, sq_hi = 0.f;
#pragma unroll
            for (int nt = 0; nt < 8; nt++) {
                float x = acc[mt][nt].x, y = acc[mt][nt].y;
                float zc = acc[mt][nt].z, w = acc[mt][nt].w;
                sum_lo += x + y;  sq_lo += x * x + y * y;
                sum_hi += zc + w; sq_hi += zc * zc + w * w;
            }
#pragma unroll
            for (int o = 1; o <= 2; o <<= 1) {
                sum_lo += __shfl_xor_sync(0xffffffffu, sum_lo, o);
                sq_lo  += __shfl_xor_sync(0xffffffffu, sq_lo,  o);
                sum_hi += __shfl_xor_sync(0xffffffffu, sum_hi, o);
                sq_hi  += __shfl_xor_sync(0xffffffffu, sq_hi,  o);
            }
            float mean_lo = sum_lo * (1.f / 64.f);
            float mean_hi = sum_hi * (1.f / 64.f);
            float var_lo = sq_lo * (1.f / 64.f) - mean_lo * mean_lo;
            float var_hi = sq_hi * (1.f / 64.f) - mean_hi * mean_hi;
            float r_lo = rsqrtf(var_lo + LN_EPS) * extra;
            float r_hi = rsqrtf(var_hi + LN_EPS) * extra;
#pragma unroll
            for (int nt = 0; nt < 8; nt++) {
                acc[mt][nt].x = (acc[mt][nt].x - mean_lo) * r_lo * scx[nt];
                acc[mt][nt].y = (acc[mt][nt].y - mean_lo) * r_lo * scy[nt];
                acc[mt][nt].z = (acc[mt][nt].z - mean_hi) * r_hi * scx[nt];
                acc[mt][nt].w = (acc[mt][nt].w - mean_hi) * r_hi * scy[nt];
            }
        }
    }

#pragma unroll
    for (int mt = 0; mt < 2; mt++) {
#pragma unroll
        for (int nt = 0; nt < 8; nt++) {
            int m = bm + wm * 32 + mt * 16 + grp;
            int n = bn + wn * 64 + nt * 8 + 2 * t4;
            if (MODE == 1) {
                *(float2*)&Cout[(size_t)m * DMODEL + n] =
                    make_float2(acc[mt][nt].x, acc[mt][nt].y);
                *(float2*)&Cout[(size_t)(m + 8) * DMODEL + n] =
                    make_float2(acc[mt][nt].z, acc[mt][nt].w);
            } else {
                int bb = m >> 11, hh = n >> 6, e = n & (HDIM - 1);
                int s_lo = m & (SLEN - 1), s_hi = (m + 8) & (SLEN - 1);
                if (z < 2) {
                    size_t base = ((size_t)((bb * NHEAD + hh) * SLEN)) * HDIM;
                    *(unsigned*)&C16[base + (size_t)s_lo * HDIM + e] =
                        packh2(acc[mt][nt].x, acc[mt][nt].y);
                    *(unsigned*)&C16[base + (size_t)s_hi * HDIM + e] =
                        packh2(acc[mt][nt].z, acc[mt][nt].w);
                } else {
                    size_t base = ((size_t)((bb * NHEAD + hh) * HDIM)) * SLEN;
                    C16[base + (size_t)e * SLEN + s_lo]       = __float2half_rn(acc[mt][nt].x);
                    C16[base + (size_t)(e + 1) * SLEN + s_lo] = __float2half_rn(acc[mt][nt].y);
                    C16[base + (size_t)e * SLEN + s_hi]       = __float2half_rn(acc[mt][nt].z);
                    C16[base + (size_t)(e + 1) * SLEN + s_hi] = __float2half_rn(acc[mt][nt].w);
                }
            }
        }
    }
}

// ---------------------------------------------------------------------------
// fp16 flash attention (q-chunked). grid.x = 8 per chunk; q0 = (bx+qoff)*128.
// ---------------------------------------------------------------------------
__global__ __launch_bounds__(256) void attn_f16(int qoff)
{
    extern __shared__ __half smh[];
    __half (*Kh)[64][AP] = (__half(*)[64][AP])smh;                    // [2][kv][e]
    __half (*Vt)[64][AP] = (__half(*)[64][AP])(smh + 2 * 64 * AP);    // [2][e][kv]

    const int tid  = threadIdx.x;
    const int warp = tid >> 5, lane = tid & 31;
    const int grp  = lane >> 2, t4 = lane & 3;
    const int m0   = warp * 16;
    const int q0   = (blockIdx.x + qoff) * 128;
    const int h    = blockIdx.y, b = blockIdx.z;
    const int lrow = lane & 15, lcol = (lane >> 4) * 8;

    const __half* qh = g_q16 + ((size_t)(b * NHEAD + h)) * SLEN * HDIM;
    const __half* kh = g_k16 + ((size_t)(b * NHEAD + h)) * SLEN * HDIM;
    const __half* vt = g_v16 + ((size_t)(b * NHEAD + h)) * HDIM * SLEN;
    const __half* bmb = g_bm + (size_t)b * SLEN * SLEN;

#pragma unroll
    for (int it = 0; it < 4; it++) {
        int f = tid + it * 256;
        int r = f >> 3, c = (f & 7) * 8;
        cp16(smh + (size_t)r * AP + c, &qh[(size_t)(q0 + r) * HDIM + c]);
    }
    CP_COMMIT();
    CP_WAIT0();
    __syncthreads();

    unsigned qa[4][4];
    {
        const __half* qptr = smh + (size_t)(m0 + lrow) * AP + lcol;
#pragma unroll
        for (int kk = 0; kk < 4; kk++)
            ldsm4(qa[kk][0], qa[kk][1], qa[kk][2], qa[kk][3], qptr + kk * 16);
    }
    __syncthreads();

#pragma unroll
    for (int it = 0; it < 2; it++) {
        int f = tid + it * 256;
        int r = f >> 3, c = (f & 7) * 8;
        cp16(&Kh[0][r][c], &kh[(size_t)r * HDIM + c]);
        cp16(&Vt[0][r][c], &vt[(size_t)r * SLEN + c]);
    }
    CP_COMMIT();

    float4 X[8];
#pragma unroll
    for (int nt = 0; nt < 8; nt++) X[nt] = make_float4(0.f, 0.f, 0.f, 0.f);
    float m_lo = NEG_BIG, m_hi = NEG_BIG, l_lo = 0.f, l_hi = 0.f;

    const __half* bm_lo_base = &bmb[(size_t)(q0 + m0 + grp) * SLEN];
    const __half* bm_hi_base = bm_lo_base + (size_t)8 * SLEN;

    const int T = SLEN / 64;       // 32
    for (int s = 0; s < T; s++) {
        CP_WAIT0();
        __syncthreads();
        if (s + 1 < T) {
            int k0n = (s + 1) * 64, stn = (s + 1) & 1;
#pragma unroll
            for (int it = 0; it < 2; it++) {
                int f = tid + it * 256;
                int r = f >> 3, c = (f & 7) * 8;
                cp16(&Kh[stn][r][c], &kh[(size_t)(k0n + r) * HDIM + c]);
                cp16(&Vt[stn][r][c], &vt[(size_t)r * SLEN + k0n + c]);
            }
            CP_COMMIT();
        }

        const int st = s & 1;
        const int k0 = s * 64;
        const __half* kptr = &Kh[st][lrow][lcol];
        const __half* vptr = &Vt[st][lrow][lcol];

        unsigned pbl[8], pbh[8];
#pragma unroll
        for (int nt = 0; nt < 8; nt++) {
            pbl[nt] = *(const unsigned*)&bm_lo_base[k0 + nt * 8 + 2 * t4];
            pbh[nt] = *(const unsigned*)&bm_hi_base[k0 + nt * 8 + 2 * t4];
        }

        float4 sv[8];
#pragma unroll
        for (int nt = 0; nt < 8; nt++) sv[nt] = make_float4(0.f, 0.f, 0.f, 0.f);
#pragma unroll
        for (int kk = 0; kk < 4; kk++) {
            const int k16 = kk * 16;
            unsigned kf[8][2];
#pragma unroll
            for (int p = 0; p < 4; p++)
                ldsm4(kf[2*p][0], kf[2*p+1][0], kf[2*p][1], kf[2*p+1][1],
                      kptr + p * 16 * AP + k16);
#pragma unroll
            for (int nt = 0; nt < 8; nt++)
                mma_f16(sv[nt], qa[kk][0], qa[kk][1], qa[kk][2], qa[kk][3],
                        kf[nt][0], kf[nt][1]);
        }

        float mx_lo = NEG_BIG, mx_hi = NEG_BIG;
#pragma unroll
        for (int nt = 0; nt < 8; nt++) {
            float2 blo = unpackh2(pbl[nt]);
            float2 bhi = unpackh2(pbh[nt]);
            sv[nt].x += blo.x; sv[nt].y += blo.y;
            sv[nt].z += bhi.x; sv[nt].w += bhi.y;
            mx_lo = fmaxf(mx_lo, fmaxf(sv[nt].x, sv[nt].y));
            mx_hi = fmaxf(mx_hi, fmaxf(sv[nt].z, sv[nt].w));
        }
        mx_lo = fmaxf(mx_lo, __shfl_xor_sync(0xffffffffu, mx_lo, 1));
        mx_lo = fmaxf(mx_lo, __shfl_xor_sync(0xffffffffu, mx_lo, 2));
        mx_hi = fmaxf(mx_hi, __shfl_xor_sync(0xffffffffu, mx_hi, 1));
        mx_hi = fmaxf(mx_hi, __shfl_xor_sync(0xffffffffu, mx_hi, 2));

        float mn_lo = fmaxf(m_lo, mx_lo), mn_hi = fmaxf(m_hi, mx_hi);
        float cor_lo = ex2(m_lo - mn_lo), cor_hi = ex2(m_hi - mn_hi);
        m_lo = mn_lo; m_hi = mn_hi;

        float rs_lo = 0.f, rs_hi = 0.f;
#pragma unroll
        for (int nt = 0; nt < 8; nt++) {
            sv[nt].x = ex2(sv[nt].x - mn_lo);
            sv[nt].y = ex2(sv[nt].y - mn_lo);
            sv[nt].z = ex2(sv[nt].z - mn_hi);
            sv[nt].w = ex2(sv[nt].w - mn_hi);
            rs_lo += sv[nt].x + sv[nt].y;
            rs_hi += sv[nt].z + sv[nt].w;
        }
        l_lo = l_lo * cor_lo + rs_lo;
        l_hi = l_hi * cor_hi + rs_hi;
#pragma unroll
        for (int nt = 0; nt < 8; nt++) {
            X[nt].x *= cor_lo; X[nt].y *= cor_lo;
            X[nt].z *= cor_hi; X[nt].w *= cor_hi;
        }

#pragma unroll
        for (int kk = 0; kk < 4; kk++) {
            const int k16 = kk * 16;
            unsigned pa0 = packh2(sv[2*kk].x,     sv[2*kk].y);
            unsigned pa1 = packh2(sv[2*kk].z,     sv[2*kk].w);
            unsigned pa2 = packh2(sv[2*kk + 1].x, sv[2*kk + 1].y);
            unsigned pa3 = packh2(sv[2*kk + 1].z, sv[2*kk + 1].w);
            unsigned vf[8][2];
#pragma unroll
            for (int p = 0; p < 4; p++)
                ldsm4(vf[2*p][0], vf[2*p+1][0], vf[2*p][1], vf[2*p+1][1],
                      vptr + p * 16 * AP + k16);
#pragma unroll
            for (int nt = 0; nt < 8; nt++)
                mma_f16(X[nt], pa0, pa1, pa2, pa3, vf[nt][0], vf[nt][1]);
        }
    }

    l_lo += __shfl_xor_sync(0xffffffffu, l_lo, 1);
    l_lo += __shfl_xor_sync(0xffffffffu, l_lo, 2);
    l_hi += __shfl_xor_sync(0xffffffffu, l_hi, 1);
    l_hi += __shfl_xor_sync(0xffffffffu, l_hi, 2);
    float il_lo = 1.f / l_lo, il_hi = 1.f / l_hi;
    int r_lo = q0 + m0 + grp, r_hi = r_lo + 8;
#pragma unroll
    for (int nt = 0; nt < 8; nt++) {
        int col = h * HDIM + nt * 8 + 2 * t4;
        *(unsigned*)&g_x16[(size_t)(b * SLEN + r_lo) * DMODEL + col] =
            packh2(X[nt].x * il_lo, X[nt].y * il_lo);
        *(unsigned*)&g_x16[(size_t)(b * SLEN + r_hi) * DMODEL + col] =
            packh2(X[nt].z * il_hi, X[nt].w * il_hi);
    }
}

// ---------------------------------------------------------------------------
extern "C" void kernel_launch(void* const* d_in, const int* in_sizes, int n_in,
                              void* d_out, int out_size)
{
    const float*         inputs_q = (const float*)d_in[0];
    const float*         bias     = (const float*)d_in[1];
    const unsigned char* mask     = (const unsigned char*)d_in[2];
    const float*         wq       = (const float*)d_in[3];
    const float*         bq       = (const float*)d_in[4];
    const float*         wk       = (const float*)d_in[5];
    const float*         bk       = (const float*)d_in[6];
    const float*         wv       = (const float*)d_in[7];
    const float*         bv       = (const float*)d_in[8];
    const float*         q_scale  = (const float*)d_in[9];
    const float*         k_scale  = (const float*)d_in[10];
    const float*         wo       = (const float*)d_in[11];
    const float*         bo       = (const float*)d_in[12];
    float*               out      = (float*)d_out;

    const int GEMM_SMEM = 2 * 2 * 128 * AP * 2;            // 73728 B
    const int ATTN_SMEM = 4 * 64 * AP * 2;                 // 36864 B

    static bool init_done = false;
    static cudaStream_t s1, s2, s3;
    static cudaEvent_t evFork, evBM, evWT, evQKV, evDone;
    static __half *p_wqT, *p_wkT, *p_wvT, *p_woT, *p_a16;
    if (!init_done) {
        cudaFuncSetAttribute(gemm_f16<0>, cudaFuncAttributeMaxDynamicSharedMemorySize, GEMM_SMEM);
        cudaFuncSetAttribute(gemm_f16<1>, cudaFuncAttributeMaxDynamicSharedMemorySize, GEMM_SMEM);
        cudaFuncSetAttribute(attn_f16, cudaFuncAttributeMaxDynamicSharedMemorySize, ATTN_SMEM);
        cudaGetSymbolAddress((void**)&p_wqT, g_wqT);
        cudaGetSymbolAddress((void**)&p_wkT, g_wkT);
        cudaGetSymbolAddress((void**)&p_wvT, g_wvT);
        cudaGetSymbolAddress((void**)&p_woT, g_woT);
        cudaGetSymbolAddress((void**)&p_a16, g_a16);
        cudaStreamCreateWithFlags(&s1, cudaStreamNonBlocking);
        cudaStreamCreateWithFlags(&s2, cudaStreamNonBlocking);
        cudaStreamCreateWithFlags(&s3, cudaStreamNonBlocking);
        cudaEventCreateWithFlags(&evFork, cudaEventDisableTiming);
        cudaEventCreateWithFlags(&evBM,   cudaEventDisableTiming);
        cudaEventCreateWithFlags(&evWT,   cudaEventDisableTiming);
        cudaEventCreateWithFlags(&evQKV,  cudaEventDisableTiming);
        cudaEventCreateWithFlags(&evDone, cudaEventDisableTiming);
        init_done = true;
    }

    // fork point
    cudaEventRecord(evFork, 0);

    // s1: bias/mask chain (feeds attention only)
    cudaStreamWaitEvent(s1, evFork, 0);
    detect_mask_kernel<<<1, 32, 0, s1>>>(mask);
    {
        const size_t N = (size_t)BATCH * SLEN * SLEN;
        prep_bm_kernel<<<(int)((N / 4 + 255) / 256), 256, 0, s1>>>(bias, mask);
    }
    cudaEventRecord(evBM, s1);

    // s2: weight transposes (feed gemm0/gemm1)
    cudaStreamWaitEvent(s2, evFork, 0);
    wtrans_kernel<<<dim3(32, 16, 4), 256, 0, s2>>>(wq, wk, wv, wo,
                                                   p_wqT, p_wkT, p_wvT, p_woT);
    cudaEventRecord(evWT, s2);

    // main: input conversion (concurrent with wtrans) -> QKV gemm
    const int A8 = BATCH * SLEN * DMODEL / 8;
    conv_half_kernel<<<(A8 + 255) / 256, 256>>>((const float4*)inputs_q, p_a16, A8);
    cudaStreamWaitEvent(0, evWT, 0);
    gemm_f16<0><<<dim3(32, 8, 3), 256, GEMM_SMEM>>>(bq, bk, bv, q_scale, k_scale,
                                                    nullptr, nullptr, 0);
    cudaEventRecord(evQKV, 0);

    // chunk A on main: attn (q < 1024) then O-proj rows for chunk A
    cudaStreamWaitEvent(0, evBM, 0);
    attn_f16<<<dim3(8, NHEAD, BATCH), 256, ATTN_SMEM>>>(0);
    gemm_f16<1><<<dim3(16, 8), 256, GEMM_SMEM>>>(nullptr, nullptr, nullptr, nullptr, nullptr,
                                                 out, bo, 0);

    // chunk B on s3: attn (q >= 1024) then O-proj rows for chunk B
    cudaStreamWaitEvent(s3, evQKV, 0);
    cudaStreamWaitEvent(s3, evBM, 0);
    attn_f16<<<dim3(8, NHEAD, BATCH), 256, ATTN_SMEM, s3>>>(8);
    gemm_f16<1><<<dim3(16, 8), 256, GEMM_SMEM, s3>>>(nullptr, nullptr, nullptr, nullptr, nullptr,
                                                     out, bo, 8);
    cudaEventRecord(evDone, s3);

    // join chunk B back into the main stream
    cudaStreamWaitEvent(0, evDone, 0);
}